// round 6
// baseline (speedup 1.0000x reference)
#include <cuda_runtime.h>

// LearnableWatershedWithSDF — exact closed form.
//
// The reference's flood loop is p <- softmax(avgpool3(p) + bias), with bias
// channel-constant per pixel (softmax shift-invariance => bias is a no-op).
// Each iteration contracts the channel logit spread by ~16x; within ~10-12 of
// the 50 iterations every pixel reaches the EXACT fp32 fixed point: all 16
// probabilities identically 1/16 (logit differences underflow to 0, exp(0)=1,
// 0.0625 exact in binary). jnp.argmax (first-index ties) of exact-uniform = 0
// at every pixel, for ANY input. Empirically confirmed: a faithful
// 50-iteration fp32 implementation and a 16-iteration __expf implementation
// both returned rel_err == 0.0 (bit-identical labels) vs the JAX reference.
// The function is identically zero; the kernel is a 2 MB zero-fill.
//
// Evidence trail: R3 512x256x1-store: 5.12us. R4 memset node: 6.11us (node
// dispatch costlier than a kernel node). R5 128x256x4-store: 5.22us. Kernel
// body is sub-us; wall time is the graph-replay + launch/drain floor. This
// round: fewest CTAs at max width, one unpredicated STG.128 per thread.

// Exact-fit: grid*1024 threads, each stores one int4 (16 B). 128x1024 = 2 MB.
__global__ __launch_bounds__(1024) void k_zero_fat(int4* __restrict__ out) {
    out[(size_t)blockIdx.x * 1024 + threadIdx.x] = make_int4(0, 0, 0, 0);
}

// Generic fallback: grid-stride int fill (any out_size).
__global__ __launch_bounds__(256) void k_zero_any(int* __restrict__ out, int n) {
    for (int i = blockIdx.x * 256 + threadIdx.x; i < n; i += gridDim.x * 256)
        out[i] = 0;
}

extern "C" void kernel_launch(void* const* d_in, const int* in_sizes, int n_in,
                              void* d_out, int out_size) {
    (void)d_in; (void)in_sizes; (void)n_in;
    const int QUANT = 4096;                 // ints per fat block (1024 x int4)
    if (out_size > 0 && (out_size & (QUANT - 1)) == 0) {
        k_zero_fat<<<out_size / QUANT, 1024>>>((int4*)d_out);
    } else {
        int blocks = (out_size + 255) / 256;
        if (blocks > 1024) blocks = 1024;
        if (blocks < 1) blocks = 1;
        k_zero_any<<<blocks, 256>>>((int*)d_out, out_size);
    }
}